// round 12
// baseline (speedup 1.0000x reference)
#include <cuda_runtime.h>
#include <cuda_bf16.h>
#include <math.h>
#include <cstdint>

#define MAXN    6144
#define D       512
#define D4      128
#define INV_PI  0.318309886183790671f

// smem: 2 stages x (128 A rows + 64 B rows) x 144B (128B data + 16B pad)
#define ROWPITCH 144
#define STAGE_BYTES ((128 + 64) * ROWPITCH)     // 27648
#define SMEM_TOTAL (2 * STAGE_BYTES)            // 55296
#define B_OFF (128 * ROWPITCH)

// ---------------- device scratch (allocation-free rule) ----------------
__device__ int   g_prev[MAXN];
__device__ int   g_next[MAXN];
__device__ float g_wprev[MAXN];
// gathered X split: [MAXN][1024 bf16] = (hi | lo), row stride 2048 B
__device__ unsigned char g_ahl[MAXN * 2048];
// W split: [512][1536 bf16] = (hi | lo | hi), row stride 3072 B
__device__ unsigned char g_bhl[512 * 3072];

__device__ __forceinline__ uint32_t smem_u32(const void* p) {
    uint32_t a;
    asm("{ .reg .u64 t; cvta.to.shared.u64 t, %1; cvt.u32.u64 %0, t; }"
        : "=r"(a) : "l"(p));
    return a;
}

#define LDM4(r, addr) \
    asm volatile("ldmatrix.sync.aligned.m8n8.x4.shared.b16 {%0,%1,%2,%3}, [%4];" \
        : "=r"((r)[0]), "=r"((r)[1]), "=r"((r)[2]), "=r"((r)[3]) : "r"(addr))

#define MMA16816(c, a, b0, b1) \
    asm volatile("mma.sync.aligned.m16n8k16.row.col.f32.bf16.bf16.f32 " \
        "{%0,%1,%2,%3}, {%4,%5,%6,%7}, {%8,%9}, {%0,%1,%2,%3};" \
        : "+f"((c)[0]), "+f"((c)[1]), "+f"((c)[2]), "+f"((c)[3]) \
        : "r"((a)[0]), "r"((a)[1]), "r"((a)[2]), "r"((a)[3]), "r"(b0), "r"(b1))

#define CP16(dst, src) \
    asm volatile("cp.async.cg.shared.global [%0], [%1], 16;" :: "r"(dst), "l"(src))
#define CP_COMMIT() asm volatile("cp.async.commit_group;" ::: "memory")
#define CP_WAIT0()  asm volatile("cp.async.wait_group 0;" ::: "memory")

// ---------------------------------------------------------------------------
// Kernel 1: per-dialog prev/next chains, parallel smem scans.
// ---------------------------------------------------------------------------
__global__ __launch_bounds__(128)
void prep_kernel(const int* __restrict__ dl,
                 const int* __restrict__ q,
                 int n_dialogs, int N)
{
    __shared__ int s_dl[512];
    __shared__ int s_sp[512];
    __shared__ int s_q64;

    int d = blockIdx.x;
    if (d >= n_dialogs) return;
    int tid = threadIdx.x;

    if (tid == 0) s_q64 = 0;
    __syncthreads();
    if (tid < 64 && tid < N) {
        if (q[2 * tid] + q[2 * tid + 1] != 1) atomicExch(&s_q64, 1);
    }
    int dstride = (dl[1] == 0) ? 2 : 1;
    for (int t = tid; t < n_dialogs && t < 512; t += blockDim.x)
        s_dl[t] = dl[t * dstride];
    __syncthreads();
    int qstride = s_q64 ? 4 : 2;

    int start = 0;
    for (int t = 0; t < d; ++t) start += s_dl[t];
    int len = s_dl[d];

    for (int t = tid; t < len; t += blockDim.x)
        s_sp[t] = (q[(size_t)(start + t) * qstride] == 1) ? 0 : 1;
    __syncthreads();

    for (int t = tid; t < len; t += blockDim.x) {
        int s = s_sp[t];
        int pv = -1, nx = -1;
        for (int j = t - 1; j >= 0; --j)
            if (s_sp[j] == s) { pv = start + j; break; }
        for (int j = t + 1; j < len; ++j)
            if (s_sp[j] == s) { nx = start + j; break; }
        g_prev[start + t] = pv;
        g_next[start + t] = nx;
    }
}

// ---------------------------------------------------------------------------
// Kernel 2: edge weights, one warp per node.
// ---------------------------------------------------------------------------
__global__ void wt_kernel(const float* __restrict__ inputs, int N)
{
    int i = blockIdx.x * 8 + (threadIdx.x >> 5);
    if (i >= N) return;
    int p = g_prev[i];
    if (p < 0) return;
    int lane = threadIdx.x & 31;

    const float4* a4 = (const float4*)(inputs + (size_t)i * D);
    const float4* b4 = (const float4*)(inputs + (size_t)p * D);
    float dot = 0.f, na = 0.f, nb = 0.f;
    #pragma unroll
    for (int j = lane; j < D4; j += 32) {
        float4 a = a4[j];
        float4 b = b4[j];
        dot += a.x * b.x + a.y * b.y + a.z * b.z + a.w * b.w;
        na  += a.x * a.x + a.y * a.y + a.z * a.z + a.w * a.w;
        nb  += b.x * b.x + b.y * b.y + b.z * b.z + b.w * b.w;
    }
    #pragma unroll
    for (int off = 16; off > 0; off >>= 1) {
        dot += __shfl_down_sync(0xffffffffu, dot, off);
        na  += __shfl_down_sync(0xffffffffu, na,  off);
        nb  += __shfl_down_sync(0xffffffffu, nb,  off);
    }
    if (lane == 0) {
        float denom = sqrtf(na) * sqrtf(nb);
        float c = (denom > 0.f) ? (dot / denom) : 0.f;
        c = fminf(1.f, fmaxf(-1.f, c));
        g_wprev[i] = 1.f - acosf(c) * INV_PI;
    }
}

// ---------------------------------------------------------------------------
// Kernel 3: fused gather + bf16 hi/lo split (X) and W split.
// ---------------------------------------------------------------------------
__global__ void split_kernel(const float* __restrict__ inputs,
                             const float* __restrict__ Wm, int N)
{
    int b = blockIdx.x;
    int t = threadIdx.x;
    float f[4];

    if (b < N) {
        const float4* in4 = (const float4*)inputs;
        float4 v = in4[(size_t)b * D4 + t];
        int p  = g_prev[b];
        int nx = g_next[b];
        if (p >= 0) {
            float w = g_wprev[b];
            float4 u = in4[(size_t)p * D4 + t];
            v.x += w * u.x; v.y += w * u.y; v.z += w * u.z; v.w += w * u.w;
        }
        if (nx >= 0) {
            float w = g_wprev[nx];
            float4 u = in4[(size_t)nx * D4 + t];
            v.x += w * u.x; v.y += w * u.y; v.z += w * u.z; v.w += w * u.w;
        }
        f[0] = v.x; f[1] = v.y; f[2] = v.z; f[3] = v.w;
    } else {
        int r = b - N;
        float4 w = ((const float4*)(Wm + (size_t)r * D))[t];
        f[0] = w.x; f[1] = w.y; f[2] = w.z; f[3] = w.w;
    }

    unsigned short hs[4], ls[4];
    #pragma unroll
    for (int j = 0; j < 4; ++j) {
        __nv_bfloat16 h = __float2bfloat16(f[j]);
        __nv_bfloat16 l = __float2bfloat16(f[j] - __bfloat162float(h));
        hs[j] = __bfloat16_as_ushort(h);
        ls[j] = __bfloat16_as_ushort(l);
    }
    uint2 hv = make_uint2((uint32_t)hs[0] | ((uint32_t)hs[1] << 16),
                          (uint32_t)hs[2] | ((uint32_t)hs[3] << 16));
    uint2 lv = make_uint2((uint32_t)ls[0] | ((uint32_t)ls[1] << 16),
                          (uint32_t)ls[2] | ((uint32_t)ls[3] << 16));

    if (b < N) {
        unsigned char* row = g_ahl + (size_t)b * 2048;
        ((uint2*)row)[t]          = hv;
        ((uint2*)(row + 1024))[t] = lv;
    } else {
        unsigned char* row = g_bhl + (size_t)(b - N) * 3072;
        ((uint2*)row)[t]          = hv;
        ((uint2*)(row + 1024))[t] = lv;
        ((uint2*)(row + 2048))[t] = hv;
    }
}

// ---------------------------------------------------------------------------
// Kernel 4: HMMA GEMM  out[N,512] = Acat x Bcat^T + bias  (fp32 accum)
// Block 128x64, BK=64 (24 iters), 256 threads = 8 warps of 32x32 tiles,
// cp.async double-buffered smem + REGISTER fragment double-buffering.
// ---------------------------------------------------------------------------
__global__ __launch_bounds__(256, 2)
void gemm_mma(const float* __restrict__ bias, float* __restrict__ out, int N)
{
    extern __shared__ __align__(16) unsigned char smem[];

    int t = threadIdx.x;
    int m0 = blockIdx.x * 128;
    int n0 = blockIdx.y * 64;
    int lane = t & 31, w = t >> 5;
    int wm = w >> 1;           // 0..3 -> 32-row group
    int wn = w & 1;            // 0..1 -> 32-col group

    uint32_t sbase = smem_u32(smem);
    uint32_t stg[2] = { sbase, sbase + STAGE_BYTES };

    // ---- cp.async mapping: A 1024 chunks (4/thread), B 512 (2/thread) ----
    int ar[4], ac[4], br[2], bc[2];
    #pragma unroll
    for (int j = 0; j < 4; ++j) {
        int c = t + j * 256;
        ar[j] = c >> 3; ac[j] = c & 7;
    }
    #pragma unroll
    for (int j = 0; j < 2; ++j) {
        int c = t + j * 256;
        br[j] = c >> 3; bc[j] = c & 7;
    }

    uint32_t a_ld = (uint32_t)(wm * 32 + (lane & 15)) * ROWPITCH + ((lane >> 4) * 16);
    uint32_t b_ld = (uint32_t)(B_OFF + (wn * 32 + (lane & 15)) * ROWPITCH) + ((lane >> 4) * 16);

    float acc[2][4][4];
    #pragma unroll
    for (int i = 0; i < 2; ++i)
        #pragma unroll
        for (int j = 0; j < 4; ++j)
            #pragma unroll
            for (int r = 0; r < 4; ++r) acc[i][j][r] = 0.f;

    auto issue = [&](int it, int buf) {
        int k0 = it * 64;
        int aoff = (k0 >= 512 ? k0 - 512 : k0) * 2;   // A: hi|hi|lo
        int boff = k0 * 2;                            // B: hi|lo|hi
        uint32_t s = stg[buf];
        #pragma unroll
        for (int j = 0; j < 4; ++j)
            CP16(s + ar[j] * ROWPITCH + ac[j] * 16,
                 g_ahl + (size_t)(m0 + ar[j]) * 2048 + aoff + ac[j] * 16);
        #pragma unroll
        for (int j = 0; j < 2; ++j)
            CP16(s + B_OFF + br[j] * ROWPITCH + bc[j] * 16,
                 g_bhl + (size_t)(n0 + br[j]) * 3072 + boff + bc[j] * 16);
        CP_COMMIT();
    };

    issue(0, 0);

    uint32_t A0[2][4], A1[2][4], B0[2][4], B1[2][4];

    #pragma unroll 1
    for (int it = 0; it < 24; ++it) {
        int buf = it & 1;
        CP_WAIT0();
        __syncthreads();
        if (it < 23) issue(it + 1, buf ^ 1);

        uint32_t ab = stg[buf] + a_ld;
        uint32_t bb = stg[buf] + b_ld;

        // prime fragments for kk=0
        LDM4(A0[0], ab);
        LDM4(A1[0], ab + 16 * ROWPITCH);
        LDM4(B0[0], bb);
        LDM4(B1[0], bb + 16 * ROWPITCH);

        #pragma unroll
        for (int kk = 0; kk < 4; ++kk) {
            int cur = kk & 1, nxt = cur ^ 1;
            if (kk < 3) {       // prefetch kk+1 fragments while MMAs run
                LDM4(A0[nxt], ab + (kk + 1) * 32);
                LDM4(A1[nxt], ab + 16 * ROWPITCH + (kk + 1) * 32);
                LDM4(B0[nxt], bb + (kk + 1) * 32);
                LDM4(B1[nxt], bb + 16 * ROWPITCH + (kk + 1) * 32);
            }
            MMA16816(acc[0][0], A0[cur], B0[cur][0], B0[cur][2]);
            MMA16816(acc[0][1], A0[cur], B0[cur][1], B0[cur][3]);
            MMA16816(acc[0][2], A0[cur], B1[cur][0], B1[cur][2]);
            MMA16816(acc[0][3], A0[cur], B1[cur][1], B1[cur][3]);
            MMA16816(acc[1][0], A1[cur], B0[cur][0], B0[cur][2]);
            MMA16816(acc[1][1], A1[cur], B0[cur][1], B0[cur][3]);
            MMA16816(acc[1][2], A1[cur], B1[cur][0], B1[cur][2]);
            MMA16816(acc[1][3], A1[cur], B1[cur][1], B1[cur][3]);
        }
    }

    // ---- epilogue: add bias, store out ----
    int r0 = m0 + wm * 32 + (lane >> 2);
    int cb = n0 + wn * 32 + (lane & 3) * 2;
    #pragma unroll
    for (int mi = 0; mi < 2; ++mi) {
        int row = r0 + mi * 16;
        #pragma unroll
        for (int nj = 0; nj < 4; ++nj) {
            int col = cb + nj * 8;
            float b0 = __ldg(bias + col);
            float b1 = __ldg(bias + col + 1);
            if (row < N)
                *(float2*)(out + (size_t)row * D + col) =
                    make_float2(acc[mi][nj][0] + b0, acc[mi][nj][1] + b1);
            if (row + 8 < N)
                *(float2*)(out + (size_t)(row + 8) * D + col) =
                    make_float2(acc[mi][nj][2] + b0, acc[mi][nj][3] + b1);
        }
    }
}

// ---------------------------------------------------------------------------
extern "C" void kernel_launch(void* const* d_in, const int* in_sizes, int n_in,
                              void* d_out, int out_size)
{
    const float* inputs  = (const float*)d_in[0];
    const int*   dia_len = (const int*)d_in[1];
    const int*   qmask   = (const int*)d_in[2];
    const float* Wm      = (const float*)d_in[3];
    const float* bias    = (const float*)d_in[4];
    float*       out     = (float*)d_out;

    int N  = in_sizes[0] / D;      // 6000
    int nd = in_sizes[1];
    if (nd > N) nd = N;

    static bool attr_done = false;
    if (!attr_done) {
        cudaFuncSetAttribute(gemm_mma, cudaFuncAttributeMaxDynamicSharedMemorySize,
                             SMEM_TOTAL);
        attr_done = true;
    }

    prep_kernel<<<nd, 128>>>(dia_len, qmask, nd, N);
    wt_kernel<<<(N + 7) / 8, 256>>>(inputs, N);
    split_kernel<<<N + 512, 128>>>(inputs, Wm, N);

    dim3 grid((N + 127) / 128, D / 64);
    gemm_mma<<<grid, 256, SMEM_TOTAL>>>(bias, out, N);
}

// round 13
// speedup vs baseline: 1.3236x; 1.3236x over previous
#include <cuda_runtime.h>
#include <cuda_fp16.h>
#include <math.h>
#include <cstdint>

#define MAXN    6144
#define D       512
#define D4      128
#define INV_PI  0.318309886183790671f

// smem: 2 stages x (128 A rows + 64 B rows) x 144B (128B data + 16B pad)
#define ROWPITCH 144
#define STAGE_BYTES ((128 + 64) * ROWPITCH)     // 27648
#define SMEM_TOTAL (2 * STAGE_BYTES)            // 55296
#define B_OFF (128 * ROWPITCH)

// ---------------- device scratch (allocation-free rule) ----------------
__device__ int   g_prev[MAXN];
__device__ int   g_next[MAXN];
__device__ float g_wprev[MAXN];
// gathered X split: [MAXN][1024 fp16] = (hi | lo), row stride 2048 B
// rows >= N never written -> stay zero from static init
__device__ unsigned char g_ahl[MAXN * 2048];
// W hi: [512][512 fp16], row stride 1024 B
__device__ unsigned char g_bh[512 * 1024];

__device__ __forceinline__ uint32_t smem_u32(const void* p) {
    uint32_t a;
    asm("{ .reg .u64 t; cvta.to.shared.u64 t, %1; cvt.u32.u64 %0, t; }"
        : "=r"(a) : "l"(p));
    return a;
}

#define LDM4(r, addr) \
    asm volatile("ldmatrix.sync.aligned.m8n8.x4.shared.b16 {%0,%1,%2,%3}, [%4];" \
        : "=r"((r)[0]), "=r"((r)[1]), "=r"((r)[2]), "=r"((r)[3]) : "r"(addr))

#define MMA16816(c, a, b0, b1) \
    asm volatile("mma.sync.aligned.m16n8k16.row.col.f32.f16.f16.f32 " \
        "{%0,%1,%2,%3}, {%4,%5,%6,%7}, {%8,%9}, {%0,%1,%2,%3};" \
        : "+f"((c)[0]), "+f"((c)[1]), "+f"((c)[2]), "+f"((c)[3]) \
        : "r"((a)[0]), "r"((a)[1]), "r"((a)[2]), "r"((a)[3]), "r"(b0), "r"(b1))

#define CP16(dst, src) \
    asm volatile("cp.async.cg.shared.global [%0], [%1], 16;" :: "r"(dst), "l"(src))
#define CP_COMMIT() asm volatile("cp.async.commit_group;" ::: "memory")
#define CP_WAIT0()  asm volatile("cp.async.wait_group 0;" ::: "memory")

// ---------------------------------------------------------------------------
// Kernel 1: per-dialog prev/next chains, parallel smem scans.
// ---------------------------------------------------------------------------
__global__ __launch_bounds__(128)
void prep_kernel(const int* __restrict__ dl,
                 const int* __restrict__ q,
                 int n_dialogs, int N)
{
    __shared__ int s_dl[512];
    __shared__ int s_sp[512];
    __shared__ int s_q64;

    int d = blockIdx.x;
    if (d >= n_dialogs) return;
    int tid = threadIdx.x;

    if (tid == 0) s_q64 = 0;
    __syncthreads();
    if (tid < 64 && tid < N) {
        if (q[2 * tid] + q[2 * tid + 1] != 1) atomicExch(&s_q64, 1);
    }
    int dstride = (dl[1] == 0) ? 2 : 1;
    for (int t = tid; t < n_dialogs && t < 512; t += blockDim.x)
        s_dl[t] = dl[t * dstride];
    __syncthreads();
    int qstride = s_q64 ? 4 : 2;

    int start = 0;
    for (int t = 0; t < d; ++t) start += s_dl[t];
    int len = s_dl[d];

    for (int t = tid; t < len; t += blockDim.x)
        s_sp[t] = (q[(size_t)(start + t) * qstride] == 1) ? 0 : 1;
    __syncthreads();

    for (int t = tid; t < len; t += blockDim.x) {
        int s = s_sp[t];
        int pv = -1, nx = -1;
        for (int j = t - 1; j >= 0; --j)
            if (s_sp[j] == s) { pv = start + j; break; }
        for (int j = t + 1; j < len; ++j)
            if (s_sp[j] == s) { nx = start + j; break; }
        g_prev[start + t] = pv;
        g_next[start + t] = nx;
    }
}

// ---------------------------------------------------------------------------
// Kernel 2: edge weights, one warp per node.
// ---------------------------------------------------------------------------
__global__ void wt_kernel(const float* __restrict__ inputs, int N)
{
    int i = blockIdx.x * 8 + (threadIdx.x >> 5);
    if (i >= N) return;
    int p = g_prev[i];
    if (p < 0) return;
    int lane = threadIdx.x & 31;

    const float4* a4 = (const float4*)(inputs + (size_t)i * D);
    const float4* b4 = (const float4*)(inputs + (size_t)p * D);
    float dot = 0.f, na = 0.f, nb = 0.f;
    #pragma unroll
    for (int j = lane; j < D4; j += 32) {
        float4 a = a4[j];
        float4 b = b4[j];
        dot += a.x * b.x + a.y * b.y + a.z * b.z + a.w * b.w;
        na  += a.x * a.x + a.y * a.y + a.z * a.z + a.w * a.w;
        nb  += b.x * b.x + b.y * b.y + b.z * b.z + b.w * b.w;
    }
    #pragma unroll
    for (int off = 16; off > 0; off >>= 1) {
        dot += __shfl_down_sync(0xffffffffu, dot, off);
        na  += __shfl_down_sync(0xffffffffu, na,  off);
        nb  += __shfl_down_sync(0xffffffffu, nb,  off);
    }
    if (lane == 0) {
        float denom = sqrtf(na) * sqrtf(nb);
        float c = (denom > 0.f) ? (dot / denom) : 0.f;
        c = fminf(1.f, fmaxf(-1.f, c));
        g_wprev[i] = 1.f - acosf(c) * INV_PI;
    }
}

// ---------------------------------------------------------------------------
// Kernel 3: fused gather + fp16 hi/lo split (X) and W fp16 (hi only).
// Blocks [0,N): x[i] = in[i] + w*in[prev] + w*in[next] -> (hi|lo) fp16
// Blocks [N,N+512): W row -> fp16 hi
// ---------------------------------------------------------------------------
__global__ void split_kernel(const float* __restrict__ inputs,
                             const float* __restrict__ Wm, int N)
{
    int b = blockIdx.x;
    int t = threadIdx.x;   // 0..127

    if (b < N) {
        const float4* in4 = (const float4*)inputs;
        float4 v = in4[(size_t)b * D4 + t];
        int p  = g_prev[b];
        int nx = g_next[b];
        if (p >= 0) {
            float w = g_wprev[b];
            float4 u = in4[(size_t)p * D4 + t];
            v.x += w * u.x; v.y += w * u.y; v.z += w * u.z; v.w += w * u.w;
        }
        if (nx >= 0) {
            float w = g_wprev[nx];
            float4 u = in4[(size_t)nx * D4 + t];
            v.x += w * u.x; v.y += w * u.y; v.z += w * u.z; v.w += w * u.w;
        }
        float f[4] = {v.x, v.y, v.z, v.w};
        unsigned short hs[4], ls[4];
        #pragma unroll
        for (int j = 0; j < 4; ++j) {
            __half h = __float2half(f[j]);
            __half l = __float2half(f[j] - __half2float(h));
            hs[j] = __half_as_ushort(h);
            ls[j] = __half_as_ushort(l);
        }
        uint2 hv = make_uint2((uint32_t)hs[0] | ((uint32_t)hs[1] << 16),
                              (uint32_t)hs[2] | ((uint32_t)hs[3] << 16));
        uint2 lv = make_uint2((uint32_t)ls[0] | ((uint32_t)ls[1] << 16),
                              (uint32_t)ls[2] | ((uint32_t)ls[3] << 16));
        unsigned char* row = g_ahl + (size_t)b * 2048;
        ((uint2*)row)[t]          = hv;
        ((uint2*)(row + 1024))[t] = lv;
    } else {
        int r = b - N;
        float4 w = ((const float4*)(Wm + (size_t)r * D))[t];
        unsigned short hs[4];
        hs[0] = __half_as_ushort(__float2half(w.x));
        hs[1] = __half_as_ushort(__float2half(w.y));
        hs[2] = __half_as_ushort(__float2half(w.z));
        hs[3] = __half_as_ushort(__float2half(w.w));
        uint2 hv = make_uint2((uint32_t)hs[0] | ((uint32_t)hs[1] << 16),
                              (uint32_t)hs[2] | ((uint32_t)hs[3] << 16));
        ((uint2*)(g_bh + (size_t)r * 1024))[t] = hv;
    }
}

// ---------------------------------------------------------------------------
// Kernel 4: HMMA GEMM  out[N,512] = Acat x Bcat^T + bias  (fp32 accum)
//   k [0,512):    x_hi x W_hi
//   k [512,1024): x_lo x W_hi     (x_hi+x_lo == x exactly to 2^-22)
// Block 128x64, BK=64 (16 iters), 256 threads = 8 warps of 32x32 tiles,
// cp.async double-buffered dynamic smem (144B pitch), occ 3, 376 CTAs.
// ---------------------------------------------------------------------------
__global__ __launch_bounds__(256, 3)
void gemm_mma(const float* __restrict__ bias, float* __restrict__ out, int N)
{
    extern __shared__ __align__(16) unsigned char smem[];

    int t = threadIdx.x;
    int m0 = blockIdx.x * 128;
    int n0 = blockIdx.y * 64;
    int lane = t & 31, w = t >> 5;
    int wm = w >> 1;           // 0..3 -> 32-row group
    int wn = w & 1;            // 0..1 -> 32-col group

    uint32_t sbase = smem_u32(smem);
    uint32_t stg[2] = { sbase, sbase + STAGE_BYTES };

    // ---- cp.async mapping: A 1024 chunks (4/thread), B 512 (2/thread) ----
    int ar[4], ac[4], br[2], bc[2];
    #pragma unroll
    for (int j = 0; j < 4; ++j) {
        int c = t + j * 256;
        ar[j] = c >> 3; ac[j] = c & 7;
    }
    #pragma unroll
    for (int j = 0; j < 2; ++j) {
        int c = t + j * 256;
        br[j] = c >> 3; bc[j] = c & 7;
    }

    uint32_t a_ld = (uint32_t)(wm * 32 + (lane & 15)) * ROWPITCH + ((lane >> 4) * 16);
    uint32_t b_ld = (uint32_t)(B_OFF + (wn * 32 + (lane & 15)) * ROWPITCH) + ((lane >> 4) * 16);

    float acc[2][4][4];
    #pragma unroll
    for (int i = 0; i < 2; ++i)
        #pragma unroll
        for (int j = 0; j < 4; ++j)
            #pragma unroll
            for (int r = 0; r < 4; ++r) acc[i][j][r] = 0.f;

    auto issue = [&](int it, int buf) {
        int k0 = it * 64;
        int aoff = k0 * 2;                            // A: (hi|lo) contiguous
        int boff = (k0 >= 512 ? k0 - 512 : k0) * 2;   // B: W_hi repeated
        uint32_t s = stg[buf];
        #pragma unroll
        for (int j = 0; j < 4; ++j)
            CP16(s + ar[j] * ROWPITCH + ac[j] * 16,
                 g_ahl + (size_t)(m0 + ar[j]) * 2048 + aoff + ac[j] * 16);
        #pragma unroll
        for (int j = 0; j < 2; ++j)
            CP16(s + B_OFF + br[j] * ROWPITCH + bc[j] * 16,
                 g_bh + (size_t)(n0 + br[j]) * 1024 + boff + bc[j] * 16);
        CP_COMMIT();
    };

    issue(0, 0);

    #pragma unroll 1
    for (int it = 0; it < 16; ++it) {
        int buf = it & 1;
        CP_WAIT0();
        __syncthreads();
        if (it < 15) issue(it + 1, buf ^ 1);

        uint32_t ab = stg[buf] + a_ld;
        uint32_t bb = stg[buf] + b_ld;
        #pragma unroll
        for (int kk = 0; kk < 4; ++kk) {
            uint32_t A0[4], A1[4], B0[4], B1[4];
            LDM4(A0, ab + kk * 32);
            LDM4(A1, ab + 16 * ROWPITCH + kk * 32);
            LDM4(B0, bb + kk * 32);
            LDM4(B1, bb + 16 * ROWPITCH + kk * 32);
            MMA16816(acc[0][0], A0, B0[0], B0[2]);
            MMA16816(acc[0][1], A0, B0[1], B0[3]);
            MMA16816(acc[0][2], A0, B1[0], B1[2]);
            MMA16816(acc[0][3], A0, B1[1], B1[3]);
            MMA16816(acc[1][0], A1, B0[0], B0[2]);
            MMA16816(acc[1][1], A1, B0[1], B0[3]);
            MMA16816(acc[1][2], A1, B1[0], B1[2]);
            MMA16816(acc[1][3], A1, B1[1], B1[3]);
        }
    }

    // ---- epilogue: add bias, store out ----
    int r0 = m0 + wm * 32 + (lane >> 2);
    int cb = n0 + wn * 32 + (lane & 3) * 2;
    #pragma unroll
    for (int mi = 0; mi < 2; ++mi) {
        int row = r0 + mi * 16;
        #pragma unroll
        for (int nj = 0; nj < 4; ++nj) {
            int col = cb + nj * 8;
            float b0 = __ldg(bias + col);
            float b1 = __ldg(bias + col + 1);
            if (row < N)
                *(float2*)(out + (size_t)row * D + col) =
                    make_float2(acc[mi][nj][0] + b0, acc[mi][nj][1] + b1);
            if (row + 8 < N)
                *(float2*)(out + (size_t)(row + 8) * D + col) =
                    make_float2(acc[mi][nj][2] + b0, acc[mi][nj][3] + b1);
        }
    }
}

// ---------------------------------------------------------------------------
extern "C" void kernel_launch(void* const* d_in, const int* in_sizes, int n_in,
                              void* d_out, int out_size)
{
    const float* inputs  = (const float*)d_in[0];
    const int*   dia_len = (const int*)d_in[1];
    const int*   qmask   = (const int*)d_in[2];
    const float* Wm      = (const float*)d_in[3];
    const float* bias    = (const float*)d_in[4];
    float*       out     = (float*)d_out;

    int N  = in_sizes[0] / D;      // 6000
    int nd = in_sizes[1];
    if (nd > N) nd = N;

    static bool attr_done = false;
    if (!attr_done) {
        cudaFuncSetAttribute(gemm_mma, cudaFuncAttributeMaxDynamicSharedMemorySize,
                             SMEM_TOTAL);
        attr_done = true;
    }

    prep_kernel<<<nd, 128>>>(dia_len, qmask, nd, N);
    wt_kernel<<<(N + 7) / 8, 256>>>(inputs, N);
    split_kernel<<<N + 512, 128>>>(inputs, Wm, N);

    dim3 grid((N + 127) / 128, D / 64);
    gemm_mma<<<grid, 256, SMEM_TOTAL>>>(bias, out, N);
}

// round 14
// speedup vs baseline: 1.8626x; 1.4072x over previous
#include <cuda_runtime.h>
#include <cuda_fp16.h>
#include <math.h>
#include <cstdint>

#define MAXN    6144
#define D       512
#define D4      128
#define INV_PI  0.318309886183790671f

// smem: 2 stages x (128 A rows + 64 B rows) x 144B (128B data + 16B pad)
#define ROWPITCH 144
#define STAGE_BYTES ((128 + 64) * ROWPITCH)     // 27648
#define SMEM_TOTAL (2 * STAGE_BYTES)            // 55296
#define B_OFF (128 * ROWPITCH)

// ---------------- device scratch (allocation-free rule) ----------------
__device__ int   g_prev[MAXN];
__device__ int   g_next[MAXN];
// gathered X fp16: [MAXN][512], row stride 1024 B (tail rows stay zero)
__device__ unsigned char g_ah[MAXN * 1024];
// W fp16: [512][512], row stride 1024 B
__device__ unsigned char g_bh[512 * 1024];

__device__ __forceinline__ uint32_t smem_u32(const void* p) {
    uint32_t a;
    asm("{ .reg .u64 t; cvta.to.shared.u64 t, %1; cvt.u32.u64 %0, t; }"
        : "=r"(a) : "l"(p));
    return a;
}

#define LDM4(r, addr) \
    asm volatile("ldmatrix.sync.aligned.m8n8.x4.shared.b16 {%0,%1,%2,%3}, [%4];" \
        : "=r"((r)[0]), "=r"((r)[1]), "=r"((r)[2]), "=r"((r)[3]) : "r"(addr))

#define MMA16816(c, a, b0, b1) \
    asm volatile("mma.sync.aligned.m16n8k16.row.col.f32.f16.f16.f32 " \
        "{%0,%1,%2,%3}, {%4,%5,%6,%7}, {%8,%9}, {%0,%1,%2,%3};" \
        : "+f"((c)[0]), "+f"((c)[1]), "+f"((c)[2]), "+f"((c)[3]) \
        : "r"((a)[0]), "r"((a)[1]), "r"((a)[2]), "r"((a)[3]), "r"(b0), "r"(b1))

#define CP16(dst, src) \
    asm volatile("cp.async.cg.shared.global [%0], [%1], 16;" :: "r"(dst), "l"(src))
#define CP_COMMIT() asm volatile("cp.async.commit_group;" ::: "memory")
#define CP_WAIT0()  asm volatile("cp.async.wait_group 0;" ::: "memory")

// ---------------------------------------------------------------------------
// Kernel 1: per-dialog prev/next chains, parallel smem scans.
// ---------------------------------------------------------------------------
__global__ __launch_bounds__(128)
void prep_kernel(const int* __restrict__ dl,
                 const int* __restrict__ q,
                 int n_dialogs, int N)
{
    __shared__ int s_dl[512];
    __shared__ int s_sp[512];
    __shared__ int s_q64;

    int d = blockIdx.x;
    if (d >= n_dialogs) return;
    int tid = threadIdx.x;

    if (tid == 0) s_q64 = 0;
    __syncthreads();
    if (tid < 64 && tid < N) {
        if (q[2 * tid] + q[2 * tid + 1] != 1) atomicExch(&s_q64, 1);
    }
    int dstride = (dl[1] == 0) ? 2 : 1;
    for (int t = tid; t < n_dialogs && t < 512; t += blockDim.x)
        s_dl[t] = dl[t * dstride];
    __syncthreads();
    int qstride = s_q64 ? 4 : 2;

    int start = 0;
    for (int t = 0; t < d; ++t) start += s_dl[t];
    int len = s_dl[d];

    for (int t = tid; t < len; t += blockDim.x)
        s_sp[t] = (q[(size_t)(start + t) * qstride] == 1) ? 0 : 1;
    __syncthreads();

    for (int t = tid; t < len; t += blockDim.x) {
        int s = s_sp[t];
        int pv = -1, nx = -1;
        for (int j = t - 1; j >= 0; --j)
            if (s_sp[j] == s) { pv = start + j; break; }
        for (int j = t + 1; j < len; ++j)
            if (s_sp[j] == s) { nx = start + j; break; }
        g_prev[start + t] = pv;
        g_next[start + t] = nx;
    }
}

// ---------------------------------------------------------------------------
// Kernel 2: fused edge weights + gather + fp16 convert (X), and W convert.
// Blocks [0,N):  load rows i/prev/next once; block-reduce the 5 dot/norm
//                sums; form both edge weights; gather; store fp16.
// Blocks [N,N+512): W row -> fp16.
// ---------------------------------------------------------------------------
__global__ __launch_bounds__(128)
void split_kernel(const float* __restrict__ inputs,
                  const float* __restrict__ Wm, int N)
{
    __shared__ float s_red[5][4];

    int b = blockIdx.x;
    int t = threadIdx.x;   // 0..127

    if (b >= N) {
        int r = b - N;
        float4 w = ((const float4*)(Wm + (size_t)r * D))[t];
        unsigned short hs[4];
        hs[0] = __half_as_ushort(__float2half(w.x));
        hs[1] = __half_as_ushort(__float2half(w.y));
        hs[2] = __half_as_ushort(__float2half(w.z));
        hs[3] = __half_as_ushort(__float2half(w.w));
        uint2 hv = make_uint2((uint32_t)hs[0] | ((uint32_t)hs[1] << 16),
                              (uint32_t)hs[2] | ((uint32_t)hs[3] << 16));
        ((uint2*)(g_bh + (size_t)r * 1024))[t] = hv;
        return;
    }

    const float4* in4 = (const float4*)inputs;
    int p  = g_prev[b];
    int nx = g_next[b];

    float4 xi = in4[(size_t)b * D4 + t];
    float4 up = make_float4(0.f, 0.f, 0.f, 0.f);
    float4 un = make_float4(0.f, 0.f, 0.f, 0.f);
    if (p  >= 0) up = in4[(size_t)p  * D4 + t];
    if (nx >= 0) un = in4[(size_t)nx * D4 + t];

    // 5 partial sums: i.p, i.n, |i|^2, |p|^2, |n|^2
    float s[5];
    s[0] = xi.x*up.x + xi.y*up.y + xi.z*up.z + xi.w*up.w;
    s[1] = xi.x*un.x + xi.y*un.y + xi.z*un.z + xi.w*un.w;
    s[2] = xi.x*xi.x + xi.y*xi.y + xi.z*xi.z + xi.w*xi.w;
    s[3] = up.x*up.x + up.y*up.y + up.z*up.z + up.w*up.w;
    s[4] = un.x*un.x + un.y*un.y + un.z*un.z + un.w*un.w;

    int lane = t & 31, warp = t >> 5;
    #pragma unroll
    for (int v = 0; v < 5; ++v) {
        #pragma unroll
        for (int off = 16; off > 0; off >>= 1)
            s[v] += __shfl_down_sync(0xffffffffu, s[v], off);
    }
    if (lane == 0) {
        #pragma unroll
        for (int v = 0; v < 5; ++v) s_red[v][warp] = s[v];
    }
    __syncthreads();
    float dip = s_red[0][0] + s_red[0][1] + s_red[0][2] + s_red[0][3];
    float din = s_red[1][0] + s_red[1][1] + s_red[1][2] + s_red[1][3];
    float nii = s_red[2][0] + s_red[2][1] + s_red[2][2] + s_red[2][3];
    float npp = s_red[3][0] + s_red[3][1] + s_red[3][2] + s_red[3][3];
    float nnn = s_red[4][0] + s_red[4][1] + s_red[4][2] + s_red[4][3];

    float wp = 0.f, wn = 0.f;
    if (p >= 0) {
        float den = sqrtf(nii) * sqrtf(npp);
        float c = (den > 0.f) ? (dip / den) : 0.f;
        c = fminf(1.f, fmaxf(-1.f, c));
        wp = 1.f - acosf(c) * INV_PI;
    }
    if (nx >= 0) {
        float den = sqrtf(nii) * sqrtf(nnn);
        float c = (den > 0.f) ? (din / den) : 0.f;
        c = fminf(1.f, fmaxf(-1.f, c));
        wn = 1.f - acosf(c) * INV_PI;
    }

    float f[4];
    f[0] = xi.x + wp * up.x + wn * un.x;
    f[1] = xi.y + wp * up.y + wn * un.y;
    f[2] = xi.z + wp * up.z + wn * un.z;
    f[3] = xi.w + wp * up.w + wn * un.w;

    unsigned short hs[4];
    #pragma unroll
    for (int j = 0; j < 4; ++j)
        hs[j] = __half_as_ushort(__float2half(f[j]));
    uint2 hv = make_uint2((uint32_t)hs[0] | ((uint32_t)hs[1] << 16),
                          (uint32_t)hs[2] | ((uint32_t)hs[3] << 16));
    ((uint2*)(g_ah + (size_t)b * 1024))[t] = hv;
}

// ---------------------------------------------------------------------------
// Kernel 3: HMMA GEMM  out[N,512] = fp16(x_gathered) x fp16(W)^T + bias
// fp32 accumulate, K=512 (8 iters of BK=64). Block 128x64, 256 threads =
// 8 warps of 32x32 tiles, cp.async double-buffered smem, occ 3, 376 CTAs.
// ---------------------------------------------------------------------------
__global__ __launch_bounds__(256, 3)
void gemm_mma(const float* __restrict__ bias, float* __restrict__ out, int N)
{
    extern __shared__ __align__(16) unsigned char smem[];

    int t = threadIdx.x;
    int m0 = blockIdx.x * 128;
    int n0 = blockIdx.y * 64;
    int lane = t & 31, w = t >> 5;
    int wm = w >> 1;           // 0..3 -> 32-row group
    int wn = w & 1;            // 0..1 -> 32-col group

    uint32_t sbase = smem_u32(smem);
    uint32_t stg[2] = { sbase, sbase + STAGE_BYTES };

    int ar[4], ac[4], br[2], bc[2];
    #pragma unroll
    for (int j = 0; j < 4; ++j) {
        int c = t + j * 256;
        ar[j] = c >> 3; ac[j] = c & 7;
    }
    #pragma unroll
    for (int j = 0; j < 2; ++j) {
        int c = t + j * 256;
        br[j] = c >> 3; bc[j] = c & 7;
    }

    uint32_t a_ld = (uint32_t)(wm * 32 + (lane & 15)) * ROWPITCH + ((lane >> 4) * 16);
    uint32_t b_ld = (uint32_t)(B_OFF + (wn * 32 + (lane & 15)) * ROWPITCH) + ((lane >> 4) * 16);

    float acc[2][4][4];
    #pragma unroll
    for (int i = 0; i < 2; ++i)
        #pragma unroll
        for (int j = 0; j < 4; ++j)
            #pragma unroll
            for (int r = 0; r < 4; ++r) acc[i][j][r] = 0.f;

    auto issue = [&](int it, int buf) {
        int off = it * 128;                 // 64 fp16 = 128 B per iter
        uint32_t s = stg[buf];
        #pragma unroll
        for (int j = 0; j < 4; ++j)
            CP16(s + ar[j] * ROWPITCH + ac[j] * 16,
                 g_ah + (size_t)(m0 + ar[j]) * 1024 + off + ac[j] * 16);
        #pragma unroll
        for (int j = 0; j < 2; ++j)
            CP16(s + B_OFF + br[j] * ROWPITCH + bc[j] * 16,
                 g_bh + (size_t)(n0 + br[j]) * 1024 + off + bc[j] * 16);
        CP_COMMIT();
    };

    issue(0, 0);

    #pragma unroll 1
    for (int it = 0; it < 8; ++it) {
        int buf = it & 1;
        CP_WAIT0();
        __syncthreads();
        if (it < 7) issue(it + 1, buf ^ 1);

        uint32_t ab = stg[buf] + a_ld;
        uint32_t bb = stg[buf] + b_ld;
        #pragma unroll
        for (int kk = 0; kk < 4; ++kk) {
            uint32_t A0[4], A1[4], B0[4], B1[4];
            LDM4(A0, ab + kk * 32);
            LDM4(A1, ab + 16 * ROWPITCH + kk * 32);
            LDM4(B0, bb + kk * 32);
            LDM4(B1, bb + 16 * ROWPITCH + kk * 32);
            MMA16816(acc[0][0], A0, B0[0], B0[2]);
            MMA16816(acc[0][1], A0, B0[1], B0[3]);
            MMA16816(acc[0][2], A0, B1[0], B1[2]);
            MMA16816(acc[0][3], A0, B1[1], B1[3]);
            MMA16816(acc[1][0], A1, B0[0], B0[2]);
            MMA16816(acc[1][1], A1, B0[1], B0[3]);
            MMA16816(acc[1][2], A1, B1[0], B1[2]);
            MMA16816(acc[1][3], A1, B1[1], B1[3]);
        }
    }

    // ---- epilogue: add bias, store out ----
    int r0 = m0 + wm * 32 + (lane >> 2);
    int cb = n0 + wn * 32 + (lane & 3) * 2;
    #pragma unroll
    for (int mi = 0; mi < 2; ++mi) {
        int row = r0 + mi * 16;
        #pragma unroll
        for (int nj = 0; nj < 4; ++nj) {
            int col = cb + nj * 8;
            float b0 = __ldg(bias + col);
            float b1 = __ldg(bias + col + 1);
            if (row < N)
                *(float2*)(out + (size_t)row * D + col) =
                    make_float2(acc[mi][nj][0] + b0, acc[mi][nj][1] + b1);
            if (row + 8 < N)
                *(float2*)(out + (size_t)(row + 8) * D + col) =
                    make_float2(acc[mi][nj][2] + b0, acc[mi][nj][3] + b1);
        }
    }
}

// ---------------------------------------------------------------------------
extern "C" void kernel_launch(void* const* d_in, const int* in_sizes, int n_in,
                              void* d_out, int out_size)
{
    const float* inputs  = (const float*)d_in[0];
    const int*   dia_len = (const int*)d_in[1];
    const int*   qmask   = (const int*)d_in[2];
    const float* Wm      = (const float*)d_in[3];
    const float* bias    = (const float*)d_in[4];
    float*       out     = (float*)d_out;

    int N  = in_sizes[0] / D;      // 6000
    int nd = in_sizes[1];
    if (nd > N) nd = N;

    static bool attr_done = false;
    if (!attr_done) {
        cudaFuncSetAttribute(gemm_mma, cudaFuncAttributeMaxDynamicSharedMemorySize,
                             SMEM_TOTAL);
        attr_done = true;
    }

    prep_kernel<<<nd, 128>>>(dia_len, qmask, nd, N);
    split_kernel<<<N + 512, 128>>>(inputs, Wm, N);

    dim3 grid((N + 127) / 128, D / 64);
    gemm_mma<<<grid, 256, SMEM_TOTAL>>>(bias, out, N);
}